// round 1
// baseline (speedup 1.0000x reference)
#include <cuda_runtime.h>
#include <math.h>

#define BS   8
#define NS   128
#define TS   2048
#define FS   32
#define LAGS 5
#define HID  64
#define KTOT (LAGS * NS)   // 640
#define KC   16            // K-chunk
#define TT   8             // timesteps per block tile
#define CT   (TT * FS)     // 256 columns per block tile
#define NTHREADS 512

// Shared memory layout (dynamic):
//  phase 1 (GEMM):   As [KC][128]  at 0        (8192 B)
//                    Xs [KC][CT]   at 8192     (16384 B)
//  phase 2 (epilog): out_s [128][CT] at 0      (131072 B)   -- overlaps phase-1 bufs (sync'd)
//                    W_s  [FS][HID]  at 131072 (8192 B)     -- no overlap, loaded at start
//                    b_s  [HID]      at 139264 (256 B)
#define SMEM_BYTES 139520

__global__ __launch_bounds__(NTHREADS, 1)
void pggcn_fused_kernel(const float* __restrict__ x,      // [B,N,T,F]
                        const float* __restrict__ A,      // [B,LAGS,N,N]
                        const float* __restrict__ W,      // [HID,F]
                        const float* __restrict__ bias,   // [HID]
                        float* __restrict__ out)          // [B,N,T,HID]
{
    extern __shared__ float smem[];
    float* As    = smem;                 // [KC][128]
    float* Xs    = smem + KC * 128;      // [KC][CT]
    float* out_s = smem;                 // [128][CT]
    float* W_s   = smem + 32768;         // [FS][HID]  (offset 131072 B / 4)
    float* b_s   = smem + 32768 + FS * HID;

    const int b   = blockIdx.y;
    const int t0  = blockIdx.x * TT;
    const int tid = threadIdx.x;
    const int tx  = tid & 31;   // 0..31 -> column micro-tile
    const int ty  = tid >> 5;   // 0..15 -> row micro-tile

    // ---- load W (transposed: W_s[f][h]) and bias into the non-overlapping region
    for (int e = tid; e < HID * FS; e += NTHREADS) {
        int h = e >> 5;            // W row
        int f = e & 31;            // W col
        W_s[f * HID + h] = W[e];
    }
    if (tid < HID) b_s[tid] = bias[tid];

    // ---- accumulators: 8x8 micro-tile
    float acc[8][8];
#pragma unroll
    for (int i = 0; i < 8; i++)
#pragma unroll
        for (int j = 0; j < 8; j++) acc[i][j] = 0.0f;

    // A load mapping: each thread loads one float4 of A per chunk
    const int a_i = tid >> 2;   // 0..127 (row i)
    const int a_q = tid & 3;    // 0..3   (kk group of 4)

    // ---- prefetch chunk 0
    float4 a_pf;
    float4 x_pf[2];
    {
        const int kb = 0, lag = 0, j0 = 0;
        a_pf = *(const float4*)(A + (((b * LAGS + lag) * NS + a_i) * NS + j0 + a_q * 4));
#pragma unroll
        for (int p = 0; p < 2; p++) {
            int idx = p * NTHREADS + tid;
            int kk  = idx >> 6;          // 0..15
            int c   = (idx & 63) * 4;    // 0..252
            int t   = t0 + (c >> 5);
            int f   = c & 31;
            int ts  = t - lag;
            if (ts >= 0)
                x_pf[p] = *(const float4*)(x + (((b * NS + j0 + kk) * TS + ts) * FS + f));
            else
                x_pf[p] = make_float4(0.f, 0.f, 0.f, 0.f);
        }
    }

    // ---- main K loop over 40 chunks of 16
    for (int kb = 0; kb < KTOT; kb += KC) {
        __syncthreads();
        // store prefetched chunk to shared
        As[(a_q * 4 + 0) * 128 + a_i] = a_pf.x;
        As[(a_q * 4 + 1) * 128 + a_i] = a_pf.y;
        As[(a_q * 4 + 2) * 128 + a_i] = a_pf.z;
        As[(a_q * 4 + 3) * 128 + a_i] = a_pf.w;
#pragma unroll
        for (int p = 0; p < 2; p++) {
            int idx = p * NTHREADS + tid;
            int kk  = idx >> 6;
            int c   = (idx & 63) * 4;
            *(float4*)(Xs + kk * CT + c) = x_pf[p];
        }
        __syncthreads();

        // prefetch next chunk (overlaps with compute below)
        if (kb + KC < KTOT) {
            const int kb2 = kb + KC;
            const int lag = kb2 >> 7;
            const int j0  = kb2 & 127;
            a_pf = *(const float4*)(A + (((b * LAGS + lag) * NS + a_i) * NS + j0 + a_q * 4));
#pragma unroll
            for (int p = 0; p < 2; p++) {
                int idx = p * NTHREADS + tid;
                int kk  = idx >> 6;
                int c   = (idx & 63) * 4;
                int t   = t0 + (c >> 5);
                int f   = c & 31;
                int ts  = t - lag;
                if (ts >= 0)
                    x_pf[p] = *(const float4*)(x + (((b * NS + j0 + kk) * TS + ts) * FS + f));
                else
                    x_pf[p] = make_float4(0.f, 0.f, 0.f, 0.f);
            }
        }

        // compute: 16 k-steps of 8x8 FMA
#pragma unroll
        for (int kk = 0; kk < KC; kk++) {
            float4 a0 = *(const float4*)(As + kk * 128 + ty * 8);
            float4 a1 = *(const float4*)(As + kk * 128 + ty * 8 + 4);
            float4 b0 = *(const float4*)(Xs + kk * CT + tx * 8);
            float4 b1 = *(const float4*)(Xs + kk * CT + tx * 8 + 4);
            float av[8] = {a0.x, a0.y, a0.z, a0.w, a1.x, a1.y, a1.z, a1.w};
            float bv[8] = {b0.x, b0.y, b0.z, b0.w, b1.x, b1.y, b1.z, b1.w};
#pragma unroll
            for (int i = 0; i < 8; i++)
#pragma unroll
                for (int j = 0; j < 8; j++)
                    acc[i][j] = fmaf(av[i], bv[j], acc[i][j]);
        }
    }

    // ---- stage accumulators to shared (overwrites GEMM buffers; sync first)
    __syncthreads();
#pragma unroll
    for (int i = 0; i < 8; i++) {
        int row = ty * 8 + i;
        float4 v0 = make_float4(acc[i][0], acc[i][1], acc[i][2], acc[i][3]);
        float4 v1 = make_float4(acc[i][4], acc[i][5], acc[i][6], acc[i][7]);
        *(float4*)(out_s + row * CT + tx * 8)     = v0;
        *(float4*)(out_s + row * CT + tx * 8 + 4) = v1;
    }
    __syncthreads();

    // ---- epilogue: y[i,t,h] = gelu( sum_f out_s[i][t*32+f] * W[h][f] + bias[h] )
    // Each thread keeps h and t fixed across its 128 iterations -> hoist W column & bias.
    {
        const int h = tid & 63;
        const int t = (tid >> 6) & (TT - 1);
        float wreg[FS];
#pragma unroll
        for (int f = 0; f < FS; f++) wreg[f] = W_s[f * HID + h];
        const float bconst = b_s[h];

        for (int e = tid; e < 128 * TT * HID; e += NTHREADS) {
            int i = e >> 9;  // row index 0..127 (h, t invariant across strides of 512)
            const float* orow = out_s + i * CT + t * FS;
            float s = bconst;
#pragma unroll
            for (int f4 = 0; f4 < FS / 4; f4++) {
                float4 o = *(const float4*)(orow + f4 * 4);
                s = fmaf(o.x, wreg[f4 * 4 + 0], s);
                s = fmaf(o.y, wreg[f4 * 4 + 1], s);
                s = fmaf(o.z, wreg[f4 * 4 + 2], s);
                s = fmaf(o.w, wreg[f4 * 4 + 3], s);
            }
            // exact GELU: 0.5 * x * (1 + erf(x / sqrt(2)))
            float g = 0.5f * s * (1.0f + erff(s * 0.70710678118654752f));
            out[((b * NS + i) * TS + (t0 + t)) * HID + h] = g;
        }
    }
}

extern "C" void kernel_launch(void* const* d_in, const int* in_sizes, int n_in,
                              void* d_out, int out_size)
{
    const float* x    = (const float*)d_in[0];   // [8,128,2048,32]
    const float* A    = (const float*)d_in[1];   // [8,5,128,128]
    const float* W    = (const float*)d_in[2];   // [64,32]
    const float* bias = (const float*)d_in[3];   // [64]
    float* out = (float*)d_out;                  // [8,128,2048,64]

    static bool attr_set = false;
    // cudaFuncSetAttribute is idempotent and not a stream op; safe under capture.
    cudaFuncSetAttribute(pggcn_fused_kernel,
                         cudaFuncAttributeMaxDynamicSharedMemorySize, SMEM_BYTES);
    (void)attr_set; (void)in_sizes; (void)n_in; (void)out_size;

    dim3 grid(TS / TT, BS);   // (256, 8)
    pggcn_fused_kernel<<<grid, NTHREADS, SMEM_BYTES>>>(x, A, W, bias, out);
}

// round 3
// speedup vs baseline: 2.5606x; 2.5606x over previous
#include <cuda_runtime.h>
#include <math.h>
#include <stdint.h>

// ---------------- problem sizes ----------------
#define BSZ   8
#define NSZ   128
#define TSZ   2048
#define FSZ   32
#define LAGS  5
#define HID   64
#define KTOT  640
#define KC    32            // K per chunk
#define NCHUNK 20
#define TT    8             // timesteps per block tile
#define NCOL  256           // TT * FSZ
#define NTHREADS 512

// ---------------- smem layout (in floats/uint32) ----------------
// As  [128][36]  tf32 bits          : 4608
// Bs  [256][36]  tf32 bits          : 9216
// G   [128][260] tf32 bits (stage2) : 33280
// W2  [64][36]   tf32 bits          : 2304
// bias[64]       float              : 64
#define AS_STRIDE 36
#define BS_STRIDE 36
#define G_STRIDE  260
#define W_STRIDE  36
#define OFF_AS   0
#define OFF_BS   (OFF_AS + 128 * AS_STRIDE)       // 4608
#define OFF_G    (OFF_BS + 256 * BS_STRIDE)       // 13824
#define OFF_W2   (OFF_G  + 128 * G_STRIDE)        // 47104
#define OFF_BIAS (OFF_W2 + 64 * W_STRIDE)         // 49408
#define SMEM_FLOATS (OFF_BIAS + 64)               // 49472
#define SMEM_BYTES  (SMEM_FLOATS * 4)             // 197888

__device__ __forceinline__ uint32_t f2tf32(float f) {
    uint32_t u;
    asm("cvt.rna.tf32.f32 %0, %1;" : "=r"(u) : "f"(f));
    return u;
}

// mma.sync m16n8k8 tf32: D = A*B + D (fp32 acc). Base PTX ISA (sm_80+), valid on sm_103.
__device__ __forceinline__ void mma_tf32(float* d, const uint32_t* a, const uint32_t* b) {
    asm volatile(
        "mma.sync.aligned.m16n8k8.row.col.f32.tf32.tf32.f32 "
        "{%0,%1,%2,%3}, {%4,%5,%6,%7}, {%8,%9}, {%0,%1,%2,%3};"
        : "+f"(d[0]), "+f"(d[1]), "+f"(d[2]), "+f"(d[3])
        : "r"(a[0]), "r"(a[1]), "r"(a[2]), "r"(a[3]), "r"(b[0]), "r"(b[1]));
}

__device__ __forceinline__ float gelu_exact(float v) {
    return 0.5f * v * (1.0f + erff(v * 0.70710678118654752440f));
}

__global__ __launch_bounds__(NTHREADS, 1)
void pggcn_mma_kernel(const float* __restrict__ x,     // [B,N,T,F]
                      const float* __restrict__ A,     // [B,LAGS,N,N]
                      const float* __restrict__ W,     // [HID,F]
                      const float* __restrict__ bias,  // [HID]
                      float* __restrict__ out)         // [B,N,T,HID]
{
    extern __shared__ uint32_t smemU[];
    float* smemF = (float*)smemU;

    const int tid = threadIdx.x;
    const int wid = tid >> 5;
    const int lid = tid & 31;
    const int lq  = lid >> 2;   // 0..7
    const int lr  = lid & 3;    // 0..3
    const int b   = blockIdx.y;
    const int t0  = blockIdx.x * TT;

    // warp tiling for stage 1: 4x4 warp grid, warp tile 32m x 64n
    const int m_base = (wid & 3) * 32;
    const int n_base = (wid >> 2) * 64;

    // ---- fill W2 (tf32) and bias
    {
        uint32_t* W2 = smemU + OFF_W2;
#pragma unroll
        for (int it = 0; it < 4; it++) {
            int idx = it * NTHREADS + tid;   // 2048 elems
            int h = idx >> 5, f = idx & 31;
            W2[h * W_STRIDE + f] = f2tf32(W[h * FSZ + f]);
        }
        if (tid < HID) smemF[OFF_BIAS + tid] = bias[tid];
    }

    // ---- stage-1 accumulators: 2 m-frags x 8 n-frags x 4 regs
    float acc[2][8][4];
#pragma unroll
    for (int i = 0; i < 2; i++)
#pragma unroll
        for (int j = 0; j < 8; j++)
#pragma unroll
            for (int k = 0; k < 4; k++) acc[i][j][k] = 0.0f;

    // prefetch registers
    float4 apf[2];
    float  bpf[16];

    // ---- prefetch chunk 0
    {
        const int lag = 0, j0 = 0;
        const float* Ag = A + ((size_t)(b * LAGS + lag) * NSZ) * NSZ + j0;
#pragma unroll
        for (int it = 0; it < 2; it++) {
            int idx = it * NTHREADS + tid;
            int m = idx >> 3, q = idx & 7;
            apf[it] = *(const float4*)(Ag + m * NSZ + q * 4);
        }
        const float* Xg = x + ((size_t)b * NSZ + j0) * TSZ * FSZ;
#pragma unroll
        for (int it = 0; it < 16; it++) {
            int idx = it * NTHREADS + tid;
            int n = idx & 255, k = idx >> 8;
            int tl = n >> 5, f = n & 31;
            int ts = t0 + tl - lag;
            bpf[it] = (ts >= 0) ? Xg[(size_t)k * (TSZ * FSZ) + ts * FSZ + f] : 0.0f;
        }
    }

    uint32_t* As = smemU + OFF_AS;
    uint32_t* Bs = smemU + OFF_BS;

    // ---- main loop over 20 K-chunks
    for (int c = 0; c < NCHUNK; c++) {
        __syncthreads();   // buffer free (previous compute done)

        // store prefetched chunk (rounded to tf32)
#pragma unroll
        for (int it = 0; it < 2; it++) {
            int idx = it * NTHREADS + tid;
            int m = idx >> 3, q = idx & 7;
            uint4 v;
            v.x = f2tf32(apf[it].x); v.y = f2tf32(apf[it].y);
            v.z = f2tf32(apf[it].z); v.w = f2tf32(apf[it].w);
            *(uint4*)(As + m * AS_STRIDE + q * 4) = v;
        }
#pragma unroll
        for (int it = 0; it < 16; it++) {
            int idx = it * NTHREADS + tid;
            int n = idx & 255, k = idx >> 8;
            Bs[n * BS_STRIDE + k] = f2tf32(bpf[it]);
        }
        __syncthreads();

        // prefetch next chunk (LDG overlaps compute below)
        if (c + 1 < NCHUNK) {
            const int kk2 = (c + 1) * KC;
            const int lag = kk2 >> 7;
            const int j0  = kk2 & 127;
            const float* Ag = A + ((size_t)(b * LAGS + lag) * NSZ) * NSZ + j0;
#pragma unroll
            for (int it = 0; it < 2; it++) {
                int idx = it * NTHREADS + tid;
                int m = idx >> 3, q = idx & 7;
                apf[it] = *(const float4*)(Ag + m * NSZ + q * 4);
            }
            const float* Xg = x + ((size_t)b * NSZ + j0) * TSZ * FSZ;
#pragma unroll
            for (int it = 0; it < 16; it++) {
                int idx = it * NTHREADS + tid;
                int n = idx & 255, k = idx >> 8;
                int tl = n >> 5, f = n & 31;
                int ts = t0 + tl - lag;
                bpf[it] = (ts >= 0) ? Xg[(size_t)k * (TSZ * FSZ) + ts * FSZ + f] : 0.0f;
            }
        }

        // compute this chunk: 4 k-groups of K=8
#pragma unroll
        for (int kg = 0; kg < 4; kg++) {
            const int cidx = kg * 8 + lr;
            uint32_t af[2][4];
#pragma unroll
            for (int mf = 0; mf < 2; mf++) {
                int r = m_base + mf * 16 + lq;
                af[mf][0] = As[r * AS_STRIDE + cidx];
                af[mf][1] = As[(r + 8) * AS_STRIDE + cidx];
                af[mf][2] = As[r * AS_STRIDE + cidx + 4];
                af[mf][3] = As[(r + 8) * AS_STRIDE + cidx + 4];
            }
#pragma unroll
            for (int nf = 0; nf < 8; nf++) {
                int n = n_base + nf * 8 + lq;
                uint32_t bf[2];
                bf[0] = Bs[n * BS_STRIDE + cidx];
                bf[1] = Bs[n * BS_STRIDE + cidx + 4];
                mma_tf32(acc[0][nf], af[0], bf);
                mma_tf32(acc[1][nf], af[1], bf);
            }
        }
    }

    // ---- write stage-1 result to G (tf32 bits), fragment -> row-major
    {
        uint32_t* G = smemU + OFF_G;
#pragma unroll
        for (int mf = 0; mf < 2; mf++) {
#pragma unroll
            for (int nf = 0; nf < 8; nf++) {
                int r = m_base + mf * 16 + lq;
                int cc = n_base + nf * 8 + 2 * lr;
                uint2 v0, v1;
                v0.x = f2tf32(acc[mf][nf][0]); v0.y = f2tf32(acc[mf][nf][1]);
                v1.x = f2tf32(acc[mf][nf][2]); v1.y = f2tf32(acc[mf][nf][3]);
                *(uint2*)(G + r * G_STRIDE + cc)       = v0;
                *(uint2*)(G + (r + 8) * G_STRIDE + cc) = v1;
            }
        }
    }
    __syncthreads();

    // ---- stage 2: per t, D2[i,h] = G[i, t*32+f] * W[h,f]; 16 warps = 8t x 2 m-halves
    {
        const uint32_t* G  = smemU + OFF_G;
        const uint32_t* W2 = smemU + OFF_W2;
        const float2* bias2 = (const float2*)(smemF + OFF_BIAS);
        const int t2  = wid >> 1;
        const int mb2 = (wid & 1) * 64;
        float* outB = out + (((size_t)b * NSZ) * TSZ + (t0 + t2)) * HID;

#pragma unroll
        for (int p = 0; p < 2; p++) {       // two halves of h (32 each)
            float acc2[4][4][4];
#pragma unroll
            for (int i = 0; i < 4; i++)
#pragma unroll
                for (int j = 0; j < 4; j++)
#pragma unroll
                    for (int k = 0; k < 4; k++) acc2[i][j][k] = 0.0f;

#pragma unroll
            for (int kg = 0; kg < 4; kg++) {
                const int ac = t2 * 32 + kg * 8 + lr;
                uint32_t af[4][4];
#pragma unroll
                for (int mf = 0; mf < 4; mf++) {
                    int r = mb2 + mf * 16 + lq;
                    af[mf][0] = G[r * G_STRIDE + ac];
                    af[mf][1] = G[(r + 8) * G_STRIDE + ac];
                    af[mf][2] = G[r * G_STRIDE + ac + 4];
                    af[mf][3] = G[(r + 8) * G_STRIDE + ac + 4];
                }
                const int wc = kg * 8 + lr;
#pragma unroll
                for (int nf = 0; nf < 4; nf++) {
                    int h = p * 32 + nf * 8 + lq;
                    uint32_t bf[2];
                    bf[0] = W2[h * W_STRIDE + wc];
                    bf[1] = W2[h * W_STRIDE + wc + 4];
#pragma unroll
                    for (int mf = 0; mf < 4; mf++)
                        mma_tf32(acc2[mf][nf], af[mf], bf);
                }
            }

            // epilogue: bias + exact GELU + 8B stores (quads form full 32B sectors)
#pragma unroll
            for (int mf = 0; mf < 4; mf++) {
#pragma unroll
                for (int nf = 0; nf < 4; nf++) {
                    int r = mb2 + mf * 16 + lq;
                    int h = p * 32 + nf * 8 + 2 * lr;
                    float2 bv = bias2[p * 16 + nf * 4 + lr];
                    float2 o0, o1;
                    o0.x = gelu_exact(acc2[mf][nf][0] + bv.x);
                    o0.y = gelu_exact(acc2[mf][nf][1] + bv.y);
                    o1.x = gelu_exact(acc2[mf][nf][2] + bv.x);
                    o1.y = gelu_exact(acc2[mf][nf][3] + bv.y);
                    *(float2*)(outB + (size_t)r * (TSZ * HID) + h)       = o0;
                    *(float2*)(outB + (size_t)(r + 8) * (TSZ * HID) + h) = o1;
                }
            }
        }
    }
}

extern "C" void kernel_launch(void* const* d_in, const int* in_sizes, int n_in,
                              void* d_out, int out_size)
{
    const float* x    = (const float*)d_in[0];   // [8,128,2048,32]
    const float* A    = (const float*)d_in[1];   // [8,5,128,128]
    const float* W    = (const float*)d_in[2];   // [64,32]
    const float* bias = (const float*)d_in[3];   // [64]
    float* out = (float*)d_out;                  // [8,128,2048,64]
    (void)in_sizes; (void)n_in; (void)out_size;

    cudaFuncSetAttribute(pggcn_mma_kernel,
                         cudaFuncAttributeMaxDynamicSharedMemorySize, SMEM_BYTES);
    dim3 grid(TSZ / TT, BSZ);   // (256, 8)
    pggcn_mma_kernel<<<grid, NTHREADS, SMEM_BYTES>>>(x, A, W, bias, out);
}

// round 4
// speedup vs baseline: 4.1534x; 1.6221x over previous
#include <cuda_runtime.h>
#include <math.h>
#include <stdint.h>

// ---------------- problem sizes ----------------
#define BSZ   8
#define NSZ   128
#define TSZ   2048
#define FSZ   32
#define LAGS  5
#define HID   64
#define TT    8              // timesteps per block tile
#define NCOL  256            // TT * FSZ (stage-1 N)
#define NTHREADS 512

// ---------------- smem layout (uint32 words; fp16 pairs packed per word) ----
// A5h [5][128][SA=20]   : 12800 words  (k-permuted fp16 pairs, 16 used + pad)
// Bx  [384][SB=20]      :  7680 words  (12 timesteps x 32f rows, 32 j k-pairs)
// G   [128][GS=132]     : 16896 words  (stage-2 input, overlaps A5h/Bx)
// W2h [64][20]          :  1280 words
// bias[64] floats       :    64 words
#define SA 20
#define SB 20
#define GS 132
#define A5_LAG 2560            // 128*20
#define OFF_A5   0
#define OFF_BX   12800
#define OFF_G    0
#define OFF_W2   20480
#define OFF_BIAS 21760
#define SMEM_WORDS 21824
#define SMEM_BYTES (SMEM_WORDS * 4)   // 87296

__device__ __forceinline__ uint32_t packh2(float lo, float hi) {
    uint32_t r;
    asm("cvt.rn.f16x2.f32 %0, %1, %2;" : "=r"(r) : "f"(hi), "f"(lo));
    return r;
}

// mma.sync m16n8k16 fp16 -> fp32 acc (base PTX ISA, valid on sm_103)
__device__ __forceinline__ void mma_f16(float* d, uint2 a_lo, uint2 a_hi, uint2 b) {
    // a0={r,k2lr..}=a_lo.x  a1={r+8}=a_hi.x  a2={r,k2lr+8..}=a_lo.y  a3=a_hi.y
    asm volatile(
        "mma.sync.aligned.m16n8k16.row.col.f32.f16.f16.f32 "
        "{%0,%1,%2,%3}, {%4,%5,%6,%7}, {%8,%9}, {%0,%1,%2,%3};"
        : "+f"(d[0]), "+f"(d[1]), "+f"(d[2]), "+f"(d[3])
        : "r"(a_lo.x), "r"(a_hi.x), "r"(a_lo.y), "r"(a_hi.y),
          "r"(b.x), "r"(b.y));
}

__device__ __forceinline__ float gelu_exact(float v) {
    return 0.5f * v * (1.0f + erff(v * 0.70710678118654752440f));
}

// k-perm: word position p within a 32-k chunk (16 words) holds k-pair
// q = kg*8 + lr + 4h  where p = kg*8 + lr*2 + h.  Fragment LDS.64 at
// row*stride + kg*8 + lr*2 then yields {frag_lo, frag_hi} directly.

__global__ __launch_bounds__(NTHREADS, 1)
void pggcn_f16_kernel(const float* __restrict__ x,     // [B,N,T,F]
                      const float* __restrict__ A,     // [B,LAGS,N,N]
                      const float* __restrict__ W,     // [HID,F]
                      const float* __restrict__ bias,  // [HID]
                      float* __restrict__ out)         // [B,N,T,HID]
{
    extern __shared__ uint32_t sm[];

    const int tid = threadIdx.x;
    const int wid = tid >> 5;
    const int lid = tid & 31;
    const int lq  = lid >> 2;   // 0..7
    const int lr  = lid & 3;    // 0..3
    const int b   = blockIdx.y;
    const int t0  = blockIdx.x * TT;

    const int m_base = (wid & 3) * 32;   // stage-1: 4x4 warp grid, tile 32m x 64n
    const int n_base = (wid >> 2) * 64;

    // ---- one-time fills: W2h (k-permuted fp16) and bias
    {
        int h = tid >> 3, pp = (tid & 7) * 2;
#pragma unroll
        for (int j = 0; j < 2; j++) {
            int p = pp + j;
            int kg = p >> 3, e = p & 7, plr = e >> 1, ph = e & 1;
            int q = kg * 8 + plr + 4 * ph;
            sm[OFF_W2 + h * 20 + p] = packh2(W[h * FSZ + 2 * q], W[h * FSZ + 2 * q + 1]);
        }
        if (tid < HID) ((float*)(sm + OFF_BIAS))[tid] = bias[tid];
    }

    float acc[2][8][4];
#pragma unroll
    for (int i = 0; i < 2; i++)
#pragma unroll
        for (int j = 0; j < 8; j++)
#pragma unroll
            for (int k = 0; k < 4; k++) acc[i][j][k] = 0.0f;

    // fill-role decode (shared by A and B fills)
    const int f_r  = tid >> 2;       // 0..127
    const int f_wq = tid & 3;        // word-quad 0..3 (words wq*4 .. wq*4+3)
    const int f_kg = f_wq >> 1;
    const int f_o  = (f_wq & 1) * 4;
    const int f_c  = f_kg * 16 + f_o; // k base for this thread's word-quad

    // ---- main loop over 4 j-chunks of 32 ----
    for (int jc = 0; jc < 4; jc++) {
        const int j0 = jc * 32;
        __syncthreads();   // previous chunk's compute done

        // A fill: 5 lags x 128 rows x 16 words
        {
            const float* Arow = A + (((size_t)b * LAGS) * NSZ + f_r) * NSZ + j0 + f_c;
#pragma unroll
            for (int lag = 0; lag < LAGS; lag++) {
                float4 lo = *(const float4*)(Arow + (size_t)lag * (NSZ * NSZ));
                float4 hi = *(const float4*)(Arow + (size_t)lag * (NSZ * NSZ) + 8);
                uint4 w;
                w.x = packh2(lo.x, lo.y);
                w.y = packh2(hi.x, hi.y);
                w.z = packh2(lo.z, lo.w);
                w.w = packh2(hi.z, hi.w);
                *(uint4*)(sm + OFF_A5 + lag * A5_LAG + f_r * SA + f_wq * 4) = w;
            }
        }
        // B fill: 384 rows (12 t x 32 f) x 16 words (32 j), zero pad for t<0
        {
#pragma unroll
            for (int it = 0; it < 3; it++) {
                int n  = it * 128 + f_r;
                int tl = n >> 5, f = n & 31;
                int ts = t0 - 4 + tl;
                uint4 w = make_uint4(0u, 0u, 0u, 0u);
                if (ts >= 0) {
                    const float* xb = x + ((size_t)(b * NSZ + j0 + f_c)) * (TSZ * FSZ)
                                        + (size_t)ts * FSZ + f;
                    const size_t RS = (size_t)TSZ * FSZ;
                    float v0 = xb[0],      v1 = xb[RS],     v2 = xb[2 * RS],  v3  = xb[3 * RS];
                    float v8 = xb[8 * RS], v9 = xb[9 * RS], vA = xb[10 * RS], vB  = xb[11 * RS];
                    w.x = packh2(v0, v1);
                    w.y = packh2(v8, v9);
                    w.z = packh2(v2, v3);
                    w.w = packh2(vA, vB);
                }
                *(uint4*)(sm + OFF_BX + n * SB + f_wq * 4) = w;
            }
        }
        __syncthreads();

        // compute: 5 lags x 2 k16-groups
#pragma unroll
        for (int lag = 0; lag < LAGS; lag++) {
            const uint32_t* As = sm + OFF_A5 + lag * A5_LAG;
            const uint32_t* Bs = sm + OFF_BX + (4 - lag) * (32 * SB);
#pragma unroll
            for (int kg = 0; kg < 2; kg++) {
                const int ka = kg * 8 + lr * 2;
                uint2 a_lo[2], a_hi[2];
#pragma unroll
                for (int mf = 0; mf < 2; mf++) {
                    int r = m_base + mf * 16 + lq;
                    a_lo[mf] = *(const uint2*)(As + r * SA + ka);
                    a_hi[mf] = *(const uint2*)(As + (r + 8) * SA + ka);
                }
#pragma unroll
                for (int nf = 0; nf < 8; nf++) {
                    int ne = n_base + nf * 8 + lq;
                    uint2 bv = *(const uint2*)(Bs + ne * SB + ka);
                    mma_f16(acc[0][nf], a_lo[0], a_hi[0], bv);
                    mma_f16(acc[1][nf], a_lo[1], a_hi[1], bv);
                }
            }
        }
    }

    // ---- stage-1 -> G (fp16, k-permuted per 32-col timestep group)
    __syncthreads();
#pragma unroll
    for (int mf = 0; mf < 2; mf++) {
#pragma unroll
        for (int nf = 0; nf < 8; nf++) {
            int r = m_base + mf * 16 + lq;
            int n = n_base + nf * 8 + 2 * lr;
            int t = n >> 5, f = n & 31;
            int q = f >> 1;
            int kg = q >> 3, u = q & 7;
            int p = kg * 8 + (u & 3) * 2 + (u >> 2);
            sm[r * GS + t * 16 + p]       = packh2(acc[mf][nf][0], acc[mf][nf][1]);
            sm[(r + 8) * GS + t * 16 + p] = packh2(acc[mf][nf][2], acc[mf][nf][3]);
        }
    }
    __syncthreads();

    // ---- stage 2: D2[r, h] = G[r, t*32+f] * W[h, f]; 16 warps = 8t x 2 m-halves
    {
        const int t2  = wid >> 1;
        const int mb2 = (wid & 1) * 64;
        const float* bias_s = (const float*)(sm + OFF_BIAS);
        float* outB = out + (((size_t)b * NSZ) * TSZ + (t0 + t2)) * HID;

#pragma unroll
        for (int ph = 0; ph < 2; ph++) {   // two halves of h
            float a2[4][4][4];
#pragma unroll
            for (int i = 0; i < 4; i++)
#pragma unroll
                for (int j = 0; j < 4; j++)
#pragma unroll
                    for (int k = 0; k < 4; k++) a2[i][j][k] = 0.0f;

#pragma unroll
            for (int kg = 0; kg < 2; kg++) {
                const int ka = kg * 8 + lr * 2;
                uint2 g_lo[4], g_hi[4];
#pragma unroll
                for (int mf = 0; mf < 4; mf++) {
                    int r = mb2 + mf * 16 + lq;
                    g_lo[mf] = *(const uint2*)(sm + r * GS + t2 * 16 + ka);
                    g_hi[mf] = *(const uint2*)(sm + (r + 8) * GS + t2 * 16 + ka);
                }
#pragma unroll
                for (int nf = 0; nf < 4; nf++) {
                    int h = ph * 32 + nf * 8 + lq;
                    uint2 wv = *(const uint2*)(sm + OFF_W2 + h * 20 + ka);
#pragma unroll
                    for (int mf = 0; mf < 4; mf++)
                        mma_f16(a2[mf][nf], g_lo[mf], g_hi[mf], wv);
                }
            }

            // epilogue: bias + exact GELU + float2 stores (quads -> 32B sectors)
#pragma unroll
            for (int mf = 0; mf < 4; mf++) {
#pragma unroll
                for (int nf = 0; nf < 4; nf++) {
                    int r = mb2 + mf * 16 + lq;
                    int h = ph * 32 + nf * 8 + 2 * lr;
                    float bx = bias_s[h], by = bias_s[h + 1];
                    float2 o0, o1;
                    o0.x = gelu_exact(a2[mf][nf][0] + bx);
                    o0.y = gelu_exact(a2[mf][nf][1] + by);
                    o1.x = gelu_exact(a2[mf][nf][2] + bx);
                    o1.y = gelu_exact(a2[mf][nf][3] + by);
                    *(float2*)(outB + (size_t)r * (TSZ * HID) + h)       = o0;
                    *(float2*)(outB + (size_t)(r + 8) * (TSZ * HID) + h) = o1;
                }
            }
        }
    }
}

extern "C" void kernel_launch(void* const* d_in, const int* in_sizes, int n_in,
                              void* d_out, int out_size)
{
    const float* x    = (const float*)d_in[0];   // [8,128,2048,32]
    const float* A    = (const float*)d_in[1];   // [8,5,128,128]
    const float* W    = (const float*)d_in[2];   // [64,32]
    const float* bias = (const float*)d_in[3];   // [64]
    float* out = (float*)d_out;                  // [8,128,2048,64]
    (void)in_sizes; (void)n_in; (void)out_size;

    cudaFuncSetAttribute(pggcn_f16_kernel,
                         cudaFuncAttributeMaxDynamicSharedMemorySize, SMEM_BYTES);
    dim3 grid(TSZ / TT, BSZ);   // (256, 8)
    pggcn_f16_kernel<<<grid, NTHREADS, SMEM_BYTES>>>(x, A, W, bias, out);
}

// round 5
// speedup vs baseline: 5.1910x; 1.2498x over previous
#include <cuda_runtime.h>
#include <cuda_fp16.h>
#include <math.h>
#include <stdint.h>

// ---------------- problem sizes ----------------
#define BSZ   8
#define NSZ   128
#define TSZ   2048
#define FSZ   32
#define LAGS  5
#define HID   64
#define TT    4              // timesteps per block tile
#define NCOL  128            // TT*FSZ
#define NCHUNK 8             // j-chunks of 16
#define JC    16
#define NTHREADS 256

// ---------------- smem layout (in __half units) ----------------
// A5 [5][128][SA=24]  : 15360 halfs (k=16 + 8 pad, 48B stride)
// Bx [256][SB=24]     :  6144 halfs (rows = (TT+4)*32, lag-shifted)
// G  [128][GS=136]    : 17408 halfs (overlaps A5+Bx after mainloop)
// W  [64][WS=40]      :  2560 halfs
// bias 64 floats
#define SA 24
#define SB 24
#define GS 136
#define WS 40
#define A5_LAG (128 * SA)              // 3072 halfs
#define OFF_A5 0
#define OFF_BX 15360
#define OFF_G  0
#define OFF_W  21504
#define OFF_BIAS_BYTES 48128           // = (OFF_W + 64*WS) * 2
#define SMEM_BYTES (OFF_BIAS_BYTES + 256)   // 48384

// ---------------- device scratch: pre-converted fp16 A ----------------
// 8*5*128*128 halfs = 655360 = 81920 uint4
__device__ uint4 g_A_h[81920];

__device__ __forceinline__ uint32_t packh2(float lo, float hi) {
    uint32_t r;
    asm("cvt.rn.f16x2.f32 %0, %1, %2;" : "=r"(r) : "f"(hi), "f"(lo));
    return r;
}

#define LDSM_X4(r0, r1, r2, r3, addr) \
    asm volatile("ldmatrix.sync.aligned.m8n8.x4.shared.b16 {%0,%1,%2,%3}, [%4];" \
        : "=r"(r0), "=r"(r1), "=r"(r2), "=r"(r3) : "r"(addr))

#define CP_ASYNC16(dst, src) \
    asm volatile("cp.async.ca.shared.global [%0], [%1], 16;" :: "r"(dst), "l"(src))

__device__ __forceinline__ void mma_f16(float* d, uint32_t a0, uint32_t a1,
                                        uint32_t a2, uint32_t a3,
                                        uint32_t b0, uint32_t b1) {
    asm volatile(
        "mma.sync.aligned.m16n8k16.row.col.f32.f16.f16.f32 "
        "{%0,%1,%2,%3}, {%4,%5,%6,%7}, {%8,%9}, {%0,%1,%2,%3};"
        : "+f"(d[0]), "+f"(d[1]), "+f"(d[2]), "+f"(d[3])
        : "r"(a0), "r"(a1), "r"(a2), "r"(a3), "r"(b0), "r"(b1));
}

__device__ __forceinline__ float gelu_exact(float v) {
    return 0.5f * v * (1.0f + erff(v * 0.70710678118654752440f));
}

__device__ __forceinline__ uint32_t smem_u32(const void* p) {
    uint32_t a;
    asm("{ .reg .u64 t; cvta.to.shared.u64 t, %1; cvt.u32.u64 %0, t; }" : "=r"(a) : "l"(p));
    return a;
}

// ---------------- prepass: A fp32 -> fp16 ----------------
__global__ void pggcn_prep(const float* __restrict__ A) {
    int i = blockIdx.x * 256 + threadIdx.x;   // 327680 half2 words
    float2 v = ((const float2*)A)[i];
    ((__half2*)g_A_h)[i] = __floats2half2_rn(v.x, v.y);
}

// ---------------- main fused kernel ----------------
__global__ __launch_bounds__(NTHREADS, 2)
void pggcn_main(const float* __restrict__ x,     // [B,N,T,F]
                const float* __restrict__ W,     // [HID,F]
                const float* __restrict__ bias,  // [HID]
                float* __restrict__ out)         // [B,N,T,HID]
{
    extern __shared__ __half smh[];
    const uint32_t sbase = smem_u32(smh);

    const int tid = threadIdx.x;
    const int wid = tid >> 5;    // 0..7
    const int lid = tid & 31;
    const int lq  = lid >> 2;
    const int lr  = lid & 3;
    const int b   = blockIdx.y;
    const int t0  = blockIdx.x * TT;

    // stage-1 warp grid: 4m x 2n; warp tile 32m x 64n
    const int m_base = (wid & 3) * 32;
    const int n_base = (wid >> 2) * 64;

    // ldmatrix lane addressing (A-style: mats [r0-7,k0-7][r8-15,k0-7][r0-7,k8-15][r8-15,k8-15])
    const int la_row = ((lid >> 3) & 1) * 8 + (lid & 7);
    const int la_k   = (lid >> 4) * 8;              // halfs
    // B-style: mats [n0-7,k0-7][n0-7,k8-15][n8-15,k0-7][n8-15,k8-15]
    const int lb_row = ((lid >> 4) & 1) * 8 + (lid & 7);
    const int lb_k   = ((lid >> 3) & 1) * 8;        // halfs

    // ---- one-time fills: W (fp16, stride 40) and bias
    {
#pragma unroll
        for (int it = 0; it < 4; it++) {
            int idx = it * NTHREADS + tid;           // 1024 words
            int h = idx >> 4, wq = idx & 15;
            uint32_t w = packh2(W[h * FSZ + 2 * wq], W[h * FSZ + 2 * wq + 1]);
            *(uint32_t*)(smh + OFF_W + h * WS + 2 * wq) = w;
        }
        if (tid < HID) ((float*)((char*)smh + OFF_BIAS_BYTES))[tid] = bias[tid];
    }

    float acc[2][8][4];
#pragma unroll
    for (int i = 0; i < 2; i++)
#pragma unroll
        for (int j = 0; j < 8; j++)
#pragma unroll
            for (int k = 0; k < 4; k++) acc[i][j][k] = 0.0f;

    // fragment base addresses (bytes)
    const uint32_t aA = sbase + 2 * (OFF_A5 + (m_base + la_row) * SA + la_k);
    const uint32_t aB = sbase + 2 * (OFF_BX + (n_base + lb_row) * SB + lb_k);

    // A cp.async role: lag = it, row i = tid>>1, 16B-half hh = tid&1
    const int cp_i  = tid >> 1;
    const int cp_hh = tid & 1;
    const __half* Ah = (const __half*)g_A_h;

    // B fill role: one row per thread
    const int bn  = tid;                 // row 0..255
    const int btl = bn >> 5;
    const int bf  = bn & 31;

    // ---- main loop: 8 j-chunks of 16 ----
    for (int jc = 0; jc < NCHUNK; jc++) {
        const int j0 = jc * JC;
        if (jc) __syncthreads();   // prior compute done before overwrite

        // A tiles via cp.async (pre-converted fp16)
#pragma unroll
        for (int lag = 0; lag < LAGS; lag++) {
            const __half* src = Ah + (((size_t)(b * LAGS + lag) * NSZ) + cp_i) * NSZ
                                   + j0 + cp_hh * 8;
            uint32_t dst = sbase + 2 * (OFF_A5 + lag * A5_LAG + cp_i * SA + cp_hh * 8);
            CP_ASYNC16(dst, src);
        }
        asm volatile("cp.async.commit_group;" ::: "memory");

        // B fill: row bn = (t,f), 16 j values -> 8 fp16x2 words
        {
            uint32_t wbuf[8];
            int ts = t0 - 4 + btl;
            if (ts >= 0) {
                const float* xb = x + (((size_t)(b * NSZ + j0)) * TSZ + ts) * FSZ + bf;
                const size_t RS = (size_t)TSZ * FSZ;
#pragma unroll
                for (int p = 0; p < 8; p++)
                    wbuf[p] = packh2(xb[(2 * p) * RS], xb[(2 * p + 1) * RS]);
            } else {
#pragma unroll
                for (int p = 0; p < 8; p++) wbuf[p] = 0u;
            }
            uint4* dst = (uint4*)(smh + OFF_BX + bn * SB);
            dst[0] = make_uint4(wbuf[0], wbuf[1], wbuf[2], wbuf[3]);
            dst[1] = make_uint4(wbuf[4], wbuf[5], wbuf[6], wbuf[7]);
        }

        asm volatile("cp.async.wait_group 0;" ::: "memory");
        __syncthreads();

        // compute: 5 lags x (2 A-ldsm + 4 B-ldsm + 16 MMA)
#pragma unroll
        for (int lag = 0; lag < LAGS; lag++) {
            const uint32_t aL = aA + lag * (A5_LAG * 2);
            const uint32_t bL = aB + (4 - lag) * (32 * SB * 2);
            uint32_t a0[4], a1[4];
            LDSM_X4(a0[0], a0[1], a0[2], a0[3], aL);
            LDSM_X4(a1[0], a1[1], a1[2], a1[3], aL + 16 * SA * 2);
#pragma unroll
            for (int nf2 = 0; nf2 < 4; nf2++) {
                uint32_t bb[4];
                LDSM_X4(bb[0], bb[1], bb[2], bb[3], bL + nf2 * (16 * SB * 2));
                mma_f16(acc[0][2 * nf2],     a0[0], a0[1], a0[2], a0[3], bb[0], bb[1]);
                mma_f16(acc[0][2 * nf2 + 1], a0[0], a0[1], a0[2], a0[3], bb[2], bb[3]);
                mma_f16(acc[1][2 * nf2],     a1[0], a1[1], a1[2], a1[3], bb[0], bb[1]);
                mma_f16(acc[1][2 * nf2 + 1], a1[0], a1[1], a1[2], a1[3], bb[2], bb[3]);
            }
        }
    }

    // ---- stage-1 acc -> G (fp16, plain [r][t*32+f] layout, stride 136)
    __syncthreads();   // all compute done before overwriting A5/Bx with G
#pragma unroll
    for (int mf = 0; mf < 2; mf++) {
#pragma unroll
        for (int nf = 0; nf < 8; nf++) {
            int r = m_base + mf * 16 + lq;
            int n = n_base + nf * 8 + 2 * lr;
            *(uint32_t*)(smh + OFF_G + r * GS + n) =
                packh2(acc[mf][nf][0], acc[mf][nf][1]);
            *(uint32_t*)(smh + OFF_G + (r + 8) * GS + n) =
                packh2(acc[mf][nf][2], acc[mf][nf][3]);
        }
    }
    __syncthreads();

    // ---- stage 2: D2[r,h] = G[r, t*32+f] * W[h,f]; 8 warps = 4t x 2 m-halves
    {
        const int t2  = wid & 3;
        const int mb2 = (wid >> 2) * 64;
        const float* bias_s = (const float*)((char*)smh + OFF_BIAS_BYTES);
        float* outB = out + (((size_t)b * NSZ) * TSZ + (t0 + t2)) * HID;

        const uint32_t gA = sbase + 2 * (OFF_G + (mb2 + la_row) * GS + t2 * 32 + la_k);
        const uint32_t wB = sbase + 2 * (OFF_W + lb_row * WS + lb_k);

#pragma unroll
        for (int ph = 0; ph < 2; ph++) {
            float a2[4][4][4];
#pragma unroll
            for (int i = 0; i < 4; i++)
#pragma unroll
                for (int j = 0; j < 4; j++)
#pragma unroll
                    for (int k = 0; k < 4; k++) a2[i][j][k] = 0.0f;

#pragma unroll
            for (int kg = 0; kg < 2; kg++) {
                uint32_t g[4][4];
#pragma unroll
                for (int mf = 0; mf < 4; mf++)
                    LDSM_X4(g[mf][0], g[mf][1], g[mf][2], g[mf][3],
                            gA + mf * (16 * GS * 2) + kg * 32);
#pragma unroll
                for (int nf2 = 0; nf2 < 2; nf2++) {
                    uint32_t wv[4];
                    LDSM_X4(wv[0], wv[1], wv[2], wv[3],
                            wB + (ph * 32 + nf2 * 16) * (WS * 2) + kg * 32);
#pragma unroll
                    for (int mf = 0; mf < 4; mf++) {
                        mma_f16(a2[mf][2 * nf2],     g[mf][0], g[mf][1], g[mf][2], g[mf][3], wv[0], wv[1]);
                        mma_f16(a2[mf][2 * nf2 + 1], g[mf][0], g[mf][1], g[mf][2], g[mf][3], wv[2], wv[3]);
                    }
                }
            }

            // epilogue: bias + exact GELU + float2 stores (quads -> 32B sectors)
#pragma unroll
            for (int mf = 0; mf < 4; mf++) {
#pragma unroll
                for (int nf = 0; nf < 4; nf++) {
                    int r = mb2 + mf * 16 + lq;
                    int h = ph * 32 + nf * 8 + 2 * lr;
                    float bx = bias_s[h], by = bias_s[h + 1];
                    float2 o0, o1;
                    o0.x = gelu_exact(a2[mf][nf][0] + bx);
                    o0.y = gelu_exact(a2[mf][nf][1] + by);
                    o1.x = gelu_exact(a2[mf][nf][2] + bx);
                    o1.y = gelu_exact(a2[mf][nf][3] + by);
                    *(float2*)(outB + (size_t)r * (TSZ * HID) + h)       = o0;
                    *(float2*)(outB + (size_t)(r + 8) * (TSZ * HID) + h) = o1;
                }
            }
        }
    }
}

extern "C" void kernel_launch(void* const* d_in, const int* in_sizes, int n_in,
                              void* d_out, int out_size)
{
    const float* x    = (const float*)d_in[0];   // [8,128,2048,32]
    const float* A    = (const float*)d_in[1];   // [8,5,128,128]
    const float* W    = (const float*)d_in[2];   // [64,32]
    const float* bias = (const float*)d_in[3];   // [64]
    float* out = (float*)d_out;                  // [8,128,2048,64]
    (void)in_sizes; (void)n_in; (void)out_size;

    cudaFuncSetAttribute(pggcn_main,
                         cudaFuncAttributeMaxDynamicSharedMemorySize, SMEM_BYTES);

    pggcn_prep<<<1280, 256>>>(A);                 // 327680 half2 words
    dim3 grid(TSZ / TT, BSZ);                     // (512, 8)
    pggcn_main<<<grid, NTHREADS, SMEM_BYTES>>>(x, W, bias, out);
}